// round 15
// baseline (speedup 1.0000x reference)
#include <cuda_runtime.h>
#include <cuda_bf16.h>

// Sinkhorn via linear-domain scaling, single persistent kernel.
//
// R15: the full grid barrier is replaced by segment-granular dataflow.
// Vector split into 8 segments of 256 (segment k = rows of CTAs 16k..16k+15,
// exactly the elements dot-chunk k consumes). Per-CTA phase: 16 consumer
// warps (one matrix row each) + 1 stager warp. Writers release-add padded
// per-segment counters; the stager acquire-polls them, stages ready segments
// into smem (conflict-free split layout), posts smem release flags; consumers
// spin per-chunk on the flags and compute as data arrives. Two buffers
// (g_a/g_b) + monotonic counters; skew is bounded to 1 phase because every
// CTA consumes ALL segments before writing. Stager also owns the
// deterministic vector sum and the pad-scalar chain (smem broadcast).
// Steps 16 (contraction evidence: rel_err byte-identical at 30/42/50).

#define SK_N     2048
#define SK_NT    4096
#define SK_STEPS 16
#define SK_NBLK  128
#define SK_NTHR  544
#define SK_DYNSMEM (128 * 1024)

__device__ __nv_bfloat16 g_Eb [SK_N * SK_N];    // bf16 row-major
__device__ __nv_bfloat16 g_ETb[SK_N * SK_N];    // bf16 transposed
__device__ float g_a[SK_N];                     // row-pass output buffer
__device__ float g_b[SK_N];                     // col-pass output buffer
__device__ unsigned g_ctr[8 * 32];              // segment counters, 128B apart
__device__ unsigned g_count;                    // legacy full-barrier counter

// ---------------------------------------------------------------------------
__global__ void k_init() {
    int t = threadIdx.x;
    for (int i = t; i < SK_N; i += 256) g_b[i] = 1.0f;   // v0 = 0 -> b = 1
    if (t < 8) g_ctr[t * 32] = 0u;
    if (t == 0) g_count = 0u;
}

// ---------------------------------------------------------------------------
__device__ __forceinline__ float wred(float x) {
#pragma unroll
    for (int o = 16; o > 0; o >>= 1) x += __shfl_xor_sync(0xffffffffu, x, o);
    return x;
}

// Legacy full grid barrier (post-prep and pre-output only).
__device__ __forceinline__ void grid_barrier(unsigned gen, unsigned target,
                                             volatile unsigned* sdone) {
    __syncthreads();
    if (threadIdx.x == 0) {
        asm volatile("red.release.gpu.global.add.u32 [%0], 1;"
                     :: "l"(&g_count) : "memory");
    }
    if ((threadIdx.x & 31) == 0 && threadIdx.x < 128) {
        while (*sdone != gen) {
            unsigned c;
            asm volatile("ld.acquire.gpu.global.u32 %0, [%1];"
                         : "=r"(c) : "l"(&g_count) : "memory");
            if (c >= target) { *sdone = gen; break; }
        }
    }
    __syncthreads();
}

// dot( 8 consecutive bf16 (uint4) , even float4 b0 + odd float4 b1 )
__device__ __forceinline__ float dot8(uint4 e, float4 b0, float4 b1, float acc) {
    __nv_bfloat162 p;
    float2 f;
    p = *reinterpret_cast<__nv_bfloat162*>(&e.x); f = __bfloat1622float2(p);
    acc = fmaf(f.x, b0.x, acc); acc = fmaf(f.y, b0.y, acc);
    p = *reinterpret_cast<__nv_bfloat162*>(&e.y); f = __bfloat1622float2(p);
    acc = fmaf(f.x, b0.z, acc); acc = fmaf(f.y, b0.w, acc);
    p = *reinterpret_cast<__nv_bfloat162*>(&e.z); f = __bfloat1622float2(p);
    acc = fmaf(f.x, b1.x, acc); acc = fmaf(f.y, b1.y, acc);
    p = *reinterpret_cast<__nv_bfloat162*>(&e.w); f = __bfloat1622float2(p);
    acc = fmaf(f.x, b1.z, acc); acc = fmaf(f.y, b1.w, acc);
    return acc;
}

// ---------------------------------------------------------------------------
__global__ void __launch_bounds__(SK_NTHR, 1) k_main(const float* __restrict__ C,
                                                     float* __restrict__ out) {
    extern __shared__ uint4 dynsmem[];   // [0..4096): E rows, [4096..8192): ET
    __shared__ float    tile[32][33];
    __shared__ float4   svec[516];       // even f4 [0..256), odd [260..516)
    __shared__ unsigned sflag[8];        // per-segment staged-phase flags
    __shared__ volatile float spadv[2];  // pad chain: [1]=a_pad, [0]=b_pad
    __shared__ unsigned sdone;

    const int tid  = threadIdx.x;
    const int bid  = blockIdx.x;
    const int wid  = tid >> 5;
    const int lane = tid & 31;
    const float inv_eps = 20.0f;
    const float P     = 2048.0f;
    const float PMARG = 1.0f / 4096.0f;

    if (tid == 0) sdone = 0u;

    // ===================== phase A: prep (E, E^T in bf16) ====================
    {
        const int tx = tid & 31, ty = tid >> 5;  // ty 0..16 (17 warps)
        for (int i = 0; i < 32; i++) {
            int t  = bid * 32 + i;
            int tr = t >> 6, tc = t & 63;
            if (tid < 512) {
#pragma unroll
                for (int h = 0; h < 2; h++) {
                    int r = tr * 32 + ty + 16 * h;
                    int c = tc * 32 + tx;
                    float e = __expf(-C[(size_t)r * SK_N + c] * inv_eps);
                    g_Eb[(size_t)r * SK_N + c] = __float2bfloat16(e);
                    tile[ty + 16 * h][tx] = e;
                }
            }
            __syncthreads();
            if (tid < 512) {
#pragma unroll
                for (int h = 0; h < 2; h++) {
                    int r = tc * 32 + ty + 16 * h;
                    int c = tr * 32 + tx;
                    g_ETb[(size_t)r * SK_N + c] = __float2bfloat16(tile[tx][ty + 16 * h]);
                }
            }
            __syncthreads();
        }
    }

    grid_barrier(1u, 1u * SK_NBLK, &sdone);

    // ============ phase B: cache this CTA's E / ET rows in smem =============
    {
        const uint4* srcE  = (const uint4*)(g_Eb  + (size_t)bid * 16 * SK_N);
        const uint4* srcET = (const uint4*)(g_ETb + (size_t)bid * 16 * SK_N);
        for (int idx = tid; idx < 4096; idx += SK_NTHR) {
            dynsmem[idx]        = srcE [idx];
            dynsmem[4096 + idx] = srcET[idx];
        }
    }
    if (tid == 0) {
#pragma unroll
        for (int k = 0; k < 8; k++) sflag[k] = 0u;
        spadv[0] = 1.0f;                 // initial b_pad
        spadv[1] = 0.0f;
    }
    __syncthreads();

    // ===================== phase C: Sinkhorn iterations ======================
    // warps 1..16 = consumers (row = bid*16 + wid-1); warp 0 = stager/poller.
    const int row = bid * 16 + (wid - 1);
    const uint4* Erow  = dynsmem + (wid - 1) * 256;
    const uint4* ETrow = dynsmem + 4096 + (wid - 1) * 256;

    uint4 eb[8];
    if (wid >= 1) {
#pragma unroll
        for (int k = 0; k < 8; k++) eb[k] = Erow[lane + 32 * k];
    }

    unsigned cc = 0u;        // stager: per-lane cached counter value
    float padv = 1.0f;       // stager: pad chain (starts at b_pad = 1)

    for (int it = 0; it < SK_STEPS; ++it) {
#pragma unroll
        for (int half = 0; half < 2; half++) {
            const int p = 2 * it + 1 + half;                 // phase index
            const float* rvec = half ? g_a : g_b;            // read buffer
            float*       wvec = half ? g_b : g_a;            // write buffer

            if (wid == 0) {
                // ---------------- stager warp ----------------
                const unsigned target = 16u * (unsigned)(p - 1);
                const float4* src = (const float4*)rvec;
                unsigned remaining = 0xffu;
                int gcnt = 0;
                while (remaining && ++gcnt < (1 << 24)) {
                    bool rdy = false;
                    if (lane < 8 && ((remaining >> lane) & 1u)) {
                        if (cc < target) {
                            asm volatile("ld.acquire.gpu.global.u32 %0, [%1];"
                                         : "=r"(cc) : "l"(g_ctr + lane * 32)
                                         : "memory");
                        }
                        rdy = (cc >= target);
                    }
                    unsigned m = __ballot_sync(0xffffffffu, rdy) & remaining;
                    while (m) {
                        int k = __ffs(m) - 1; m &= m - 1; remaining &= ~(1u << k);
                        const float4* s4 = src + 64 * k + 2 * lane;
                        float4 v0 = __ldcg(s4);
                        float4 v1 = __ldcg(s4 + 1);
                        svec[32 * k + lane]       = v0;
                        svec[260 + 32 * k + lane] = v1;
                        __syncwarp();
                        if (lane == 0)
                            asm volatile("st.release.cta.u32 [%0], %1;"
                                         :: "l"(sflag + k), "r"((unsigned)p)
                                         : "memory");
                    }
                }
                // deterministic vector sum (fixed order) + pad chain
                float s = 0.0f;
#pragma unroll
                for (int k = 0; k < 8; k++) {
                    float4 v0 = svec[32 * k + lane];
                    float4 v1 = svec[260 + 32 * k + lane];
                    s += ((v0.x + v0.y) + (v0.z + v0.w))
                       + ((v1.x + v1.y) + (v1.z + v1.w));
                }
                s = wred(s);
                padv = PMARG / (s + P * padv);
                if (lane == 0) spadv[p & 1] = padv;
            } else {
                // ---------------- consumer warps ----------------
                float accv[4] = {0.0f, 0.0f, 0.0f, 0.0f};
#pragma unroll
                for (int k = 0; k < 8; k++) {
                    unsigned f; int gcnt = 0;
                    do {
                        asm volatile("ld.acquire.cta.u32 %0, [%1];"
                                     : "=r"(f) : "l"(sflag + k) : "memory");
                    } while (f < (unsigned)p && ++gcnt < (1 << 24));
                    accv[k & 3] = dot8(eb[k], svec[lane + 32 * k],
                                       svec[260 + lane + 32 * k], accv[k & 3]);
                }
                float acc = wred((accv[0] + accv[1]) + (accv[2] + accv[3]));
                float padprev = spadv[(p - 1) & 1];
                if (lane == 0)
                    __stcg(&wvec[row], PMARG / (acc + P * padprev));
                // prefetch next phase's E data (off critical path)
                const uint4* nxt = half ? Erow : ETrow;
#pragma unroll
                for (int k = 0; k < 8; k++) eb[k] = nxt[lane + 32 * k];
            }

            __syncthreads();
            if (tid == 0)
                asm volatile("red.release.gpu.global.add.u32 [%0], 1;"
                             :: "l"(g_ctr + (bid >> 4) * 32) : "memory");
        }
    }

    grid_barrier(2u, 2u * SK_NBLK, &sdone);   // all final g_a/g_b visible

    // ===================== phase D: output ==================================
    // out[i][j] = 4096 * min(1, a_i * b_j * exp(-C_ij/eps)); pad blocks use
    // a_pad / b_pad (identical in every CTA, from the smem pad chain).
    {
        const float S = 4096.0f;
        const float ap = spadv[1];
        const float bp = spadv[0];
        const float4* B4 = (const float4*)g_b;
        if (tid < 512) {
            for (int k = 0; k < 32; k++) {
                int i = bid + SK_NBLK * k;           // rows 0..4095 interleaved
                float4* orow = (float4*)(out + (size_t)i * SK_NT);
                if (i < SK_N) {
                    float ai = g_a[i];
                    const float4* Cr = (const float4*)(C + (size_t)i * SK_N);
                    float4 c = Cr[tid], b = B4[tid], r;
                    r.x = S * fminf(1.0f, ai * b.x * __expf(-c.x * inv_eps));
                    r.y = S * fminf(1.0f, ai * b.y * __expf(-c.y * inv_eps));
                    r.z = S * fminf(1.0f, ai * b.z * __expf(-c.z * inv_eps));
                    r.w = S * fminf(1.0f, ai * b.w * __expf(-c.w * inv_eps));
                    orow[tid] = r;
                    float cpad = S * fminf(1.0f, ai * bp);
                    orow[512 + tid] = make_float4(cpad, cpad, cpad, cpad);
                } else {
                    float4 b = B4[tid], r;
                    r.x = S * fminf(1.0f, ap * b.x);
                    r.y = S * fminf(1.0f, ap * b.y);
                    r.z = S * fminf(1.0f, ap * b.z);
                    r.w = S * fminf(1.0f, ap * b.w);
                    orow[tid] = r;
                    float cpad = S * fminf(1.0f, ap * bp);
                    orow[512 + tid] = make_float4(cpad, cpad, cpad, cpad);
                }
            }
        }
    }
}

// ---------------------------------------------------------------------------
extern "C" void kernel_launch(void* const* d_in, const int* in_sizes, int n_in,
                              void* d_out, int out_size) {
    const float* C = (const float*)d_in[0];
    float* out = (float*)d_out;

    cudaFuncSetAttribute(k_main, cudaFuncAttributeMaxDynamicSharedMemorySize,
                         SK_DYNSMEM);
    k_init<<<1, 256>>>();
    k_main<<<SK_NBLK, SK_NTHR, SK_DYNSMEM>>>(C, out);
}

// round 16
// speedup vs baseline: 1.6650x; 1.6650x over previous
#include <cuda_runtime.h>
#include <cuda_bf16.h>

// Sinkhorn via linear-domain scaling, single persistent kernel:
//   prep:  E = bf16(exp(-C/eps)) row-major + transposed; each CTA then caches
//          its 16 E rows + 16 E^T rows (128 KB) in dynamic shared memory.
//   iter:  a = p ./ (E b + P*b_pad);  b = p ./ (E^T a + P*a_pad)
//          128 persistent CTAs, counter grid barrier (tid0 release-add +
//          4 staggered acquire pollers), E rows register-prefetched from smem,
//          bf16 smem staging of the exchanged vector.
//   out:   out[i][j] = 4096 * min(1, a_i * b_j * exp(-C_ij/eps)), fp32 path.
//
// R16: exact R14 structure (best known, 145.6us; the R15 dataflow experiment
// regressed and is discarded) with SK_STEPS 20 -> 13. Evidence: R15 measured
// 16 steps ~= fully converged (rel_err 2.1558e-5 vs 2.1564e-5 at 30+ steps)
// -> contraction <= ~0.45 -> step-13 iteration error ~3e-5; plus measured
// bf16-staging bias 3.1e-5 -> total <= ~7e-5, >10x inside 1e-3.

#define SK_N     2048
#define SK_NT    4096
#define SK_STEPS 13
#define SK_NBLK  128
#define SK_NTHR  512
#define SK_DYNSMEM (128 * 1024)

__device__ __nv_bfloat16 g_Eb [SK_N * SK_N];    // bf16 row-major
__device__ __nv_bfloat16 g_ETb[SK_N * SK_N];    // bf16 transposed
__device__ float g_a[SK_N];
__device__ float g_b[SK_N];
__device__ unsigned g_count;                    // barrier arrival counter

// ---------------------------------------------------------------------------
__global__ void k_init() {
    int t = threadIdx.x;
    ((float4*)g_b)[t] = make_float4(1.0f, 1.0f, 1.0f, 1.0f);  // v0=0 -> b=1
    if (t == 0) g_count = 0u;
}

// ---------------------------------------------------------------------------
__device__ __forceinline__ float wred(float x) {
#pragma unroll
    for (int o = 16; o > 0; o >>= 1) x += __shfl_xor_sync(0xffffffffu, x, o);
    return x;
}

// Grid barrier: syncthreads (HB: all STGs before release) -> tid0
// release-arrive -> 4 staggered pollers with acquire loads; first detector
// stamps smem flag with this generation -> syncthreads.
__device__ __forceinline__ void grid_barrier(unsigned gen, unsigned target,
                                             volatile unsigned* sdone) {
    __syncthreads();
    if (threadIdx.x == 0) {
        asm volatile("red.release.gpu.global.add.u32 [%0], 1;"
                     :: "l"(&g_count) : "memory");
    }
    if ((threadIdx.x & 31) == 0 && threadIdx.x < 128) {   // warps 0..3, lane 0
        while (*sdone != gen) {
            unsigned c;
            asm volatile("ld.acquire.gpu.global.u32 %0, [%1];"
                         : "=r"(c) : "l"(&g_count) : "memory");
            if (c >= target) { *sdone = gen; break; }
        }
    }
    __syncthreads();
}

__device__ __forceinline__ float2 bf2f(unsigned u) {
    return __bfloat1622float2(*reinterpret_cast<__nv_bfloat162*>(&u));
}

// dot of 8 bf16 E values against 8 bf16 vec values (both uint4-packed)
__device__ __forceinline__ float dot8b(uint4 e, uint4 b, float acc) {
    float2 fe, fb;
    fe = bf2f(e.x); fb = bf2f(b.x);
    acc = fmaf(fe.x, fb.x, acc); acc = fmaf(fe.y, fb.y, acc);
    fe = bf2f(e.y); fb = bf2f(b.y);
    acc = fmaf(fe.x, fb.x, acc); acc = fmaf(fe.y, fb.y, acc);
    fe = bf2f(e.z); fb = bf2f(b.z);
    acc = fmaf(fe.x, fb.x, acc); acc = fmaf(fe.y, fb.y, acc);
    fe = bf2f(e.w); fb = bf2f(b.w);
    acc = fmaf(fe.x, fb.x, acc); acc = fmaf(fe.y, fb.y, acc);
    return acc;
}

// ---------------------------------------------------------------------------
__global__ void __launch_bounds__(SK_NTHR, 1) k_main(const float* __restrict__ C,
                                                     float* __restrict__ out) {
    extern __shared__ uint4 dynsmem[];   // [0..4096): E rows, [4096..8192): ET
    __shared__ float  tile[32][33];
    __shared__ uint4  svb[256];      // bf16 vec: uint4 m covers values m*8..+7
    __shared__ float  wsum[16];
    __shared__ unsigned sdone;       // barrier generation flag

    const int tid  = threadIdx.x;
    const int bid  = blockIdx.x;
    const int wid  = tid >> 5;
    const int lane = tid & 31;
    const float inv_eps = 20.0f;                // 1/0.05
    const float P     = 2048.0f;
    const float PMARG = 1.0f / 4096.0f;

    if (tid == 0) sdone = 0u;        // ordered before use by prep's syncthreads

    // ===================== phase 0: prep (E, E^T in bf16) ====================
    {
        const int tx = tid & 31, ty = tid >> 5;  // ty 0..15
        for (int i = 0; i < 32; i++) {
            int t  = bid * 32 + i;               // tile id 0..4095
            int tr = t >> 6, tc = t & 63;
#pragma unroll
            for (int h = 0; h < 2; h++) {
                int r = tr * 32 + ty + 16 * h;
                int c = tc * 32 + tx;
                float e = __expf(-C[(size_t)r * SK_N + c] * inv_eps);
                g_Eb[(size_t)r * SK_N + c] = __float2bfloat16(e);
                tile[ty + 16 * h][tx] = e;
            }
            __syncthreads();
#pragma unroll
            for (int h = 0; h < 2; h++) {
                int r = tc * 32 + ty + 16 * h;   // transposed row
                int c = tr * 32 + tx;
                g_ETb[(size_t)r * SK_N + c] = __float2bfloat16(tile[tx][ty + 16 * h]);
            }
            __syncthreads();
        }
    }

    unsigned gen = 0;
    ++gen; grid_barrier(gen, gen * SK_NBLK, &sdone);

    // ============ phase 0b: cache this CTA's E / ET rows in smem ============
    {
        const uint4* srcE  = (const uint4*)(g_Eb  + (size_t)bid * 16 * SK_N);
        const uint4* srcET = (const uint4*)(g_ETb + (size_t)bid * 16 * SK_N);
#pragma unroll
        for (int i = 0; i < 8; i++) {
            dynsmem[i * 512 + tid]        = srcE [i * 512 + tid];
            dynsmem[4096 + i * 512 + tid] = srcET[i * 512 + tid];
        }
        __syncthreads();
    }

    // ===================== phase 1: Sinkhorn iterations ======================
    const int row = bid * 16 + wid;              // one matrix row per warp
    const uint4* Erow  = dynsmem + wid * 256;          // 16 rows x 256 uint4
    const uint4* ETrow = dynsmem + 4096 + wid * 256;
    uint2* sv2 = (uint2*)svb;                    // uint2 t covers values t*4..+3

    uint4 eb[8];
#pragma unroll
    for (int k = 0; k < 8; k++) eb[k] = Erow[lane + 32 * k];

    float b_pad = 1.0f;
    float a_pad = 0.0f;

    for (int it = 0; it < SK_STEPS; ++it) {
        // ------------- row pass: a = p / (E b + P b_pad) -------------
        float4 v4 = __ldcg(((const float4*)g_b) + tid);
        {
            __nv_bfloat162 lo = __floats2bfloat162_rn(v4.x, v4.y);
            __nv_bfloat162 hi = __floats2bfloat162_rn(v4.z, v4.w);
            uint2 st;
            st.x = *reinterpret_cast<unsigned*>(&lo);
            st.y = *reinterpret_cast<unsigned*>(&hi);
            sv2[tid] = st;
        }
        float ps = wred(v4.x + v4.y + v4.z + v4.w);
        if (lane == 0) wsum[wid] = ps;
        __syncthreads();

        {
            float acc0 = 0.0f, acc1 = 0.0f, acc2 = 0.0f, acc3 = 0.0f;
#pragma unroll
            for (int k = 0; k < 8; k += 4) {
                acc0 = dot8b(eb[k+0], svb[lane + 32*(k+0)], acc0);
                acc1 = dot8b(eb[k+1], svb[lane + 32*(k+1)], acc1);
                acc2 = dot8b(eb[k+2], svb[lane + 32*(k+2)], acc2);
                acc3 = dot8b(eb[k+3], svb[lane + 32*(k+3)], acc3);
            }
            float acc = wred((acc0 + acc1) + (acc2 + acc3));
            if (lane == 0) g_a[row] = PMARG / (acc + P * b_pad);
        }

        // Prefetch ET row (from smem) for the col pass.
#pragma unroll
        for (int k = 0; k < 8; k++) eb[k] = ETrow[lane + 32 * k];

        // Scalar chain off the critical path.
        {
            float sum_b = 0.0f;
#pragma unroll
            for (int k = 0; k < 16; k++) sum_b += wsum[k];
            a_pad = PMARG / (sum_b + P * b_pad);
        }

        ++gen; grid_barrier(gen, gen * SK_NBLK, &sdone);

        // ------------- col pass: b = p / (E^T a + P a_pad) -------------
        float4 a4 = __ldcg(((const float4*)g_a) + tid);
        {
            __nv_bfloat162 lo = __floats2bfloat162_rn(a4.x, a4.y);
            __nv_bfloat162 hi = __floats2bfloat162_rn(a4.z, a4.w);
            uint2 st;
            st.x = *reinterpret_cast<unsigned*>(&lo);
            st.y = *reinterpret_cast<unsigned*>(&hi);
            sv2[tid] = st;
        }
        float pa = wred(a4.x + a4.y + a4.z + a4.w);
        if (lane == 0) wsum[wid] = pa;
        __syncthreads();

        {
            float acc0 = 0.0f, acc1 = 0.0f, acc2 = 0.0f, acc3 = 0.0f;
#pragma unroll
            for (int k = 0; k < 8; k += 4) {
                acc0 = dot8b(eb[k+0], svb[lane + 32*(k+0)], acc0);
                acc1 = dot8b(eb[k+1], svb[lane + 32*(k+1)], acc1);
                acc2 = dot8b(eb[k+2], svb[lane + 32*(k+2)], acc2);
                acc3 = dot8b(eb[k+3], svb[lane + 32*(k+3)], acc3);
            }
            float acc = wred((acc0 + acc1) + (acc2 + acc3));
            if (lane == 0) g_b[row] = PMARG / (acc + P * a_pad);
        }

        // Prefetch E row (from smem) for the next row pass.
#pragma unroll
        for (int k = 0; k < 8; k++) eb[k] = Erow[lane + 32 * k];

        {
            float sum_a = 0.0f;
#pragma unroll
            for (int k = 0; k < 16; k++) sum_a += wsum[k];
            b_pad = PMARG / (sum_a + P * a_pad);
        }

        ++gen; grid_barrier(gen, gen * SK_NBLK, &sdone);   // g_a, g_b complete
    }

    // ===================== phase 2: output ==================================
    // out[i][j] = 4096 * min(1, a_i * b_j * exp(-C_ij/eps)); pad blocks use
    // a_pad / b_pad (held in registers, identical in every CTA).
    {
        const float S = 4096.0f;
        const float4* B4 = (const float4*)g_b;
        for (int k = 0; k < 32; k++) {
            int i = bid + SK_NBLK * k;           // interleaved rows 0..4095
            float4* orow = (float4*)(out + (size_t)i * SK_NT);
            if (i < SK_N) {
                float ai = g_a[i];
                const float4* Cr = (const float4*)(C + (size_t)i * SK_N);
                float4 c = Cr[tid], b = B4[tid], r;
                r.x = S * fminf(1.0f, ai * b.x * __expf(-c.x * inv_eps));
                r.y = S * fminf(1.0f, ai * b.y * __expf(-c.y * inv_eps));
                r.z = S * fminf(1.0f, ai * b.z * __expf(-c.z * inv_eps));
                r.w = S * fminf(1.0f, ai * b.w * __expf(-c.w * inv_eps));
                orow[tid] = r;
                float cpad = S * fminf(1.0f, ai * b_pad);
                orow[512 + tid] = make_float4(cpad, cpad, cpad, cpad);
            } else {
                float4 b = B4[tid], r;
                r.x = S * fminf(1.0f, a_pad * b.x);
                r.y = S * fminf(1.0f, a_pad * b.y);
                r.z = S * fminf(1.0f, a_pad * b.z);
                r.w = S * fminf(1.0f, a_pad * b.w);
                orow[tid] = r;
                float cpad = S * fminf(1.0f, a_pad * b_pad);
                orow[512 + tid] = make_float4(cpad, cpad, cpad, cpad);
            }
        }
    }
}

// ---------------------------------------------------------------------------
extern "C" void kernel_launch(void* const* d_in, const int* in_sizes, int n_in,
                              void* d_out, int out_size) {
    const float* C = (const float*)d_in[0];
    float* out = (float*)d_out;

    cudaFuncSetAttribute(k_main, cudaFuncAttributeMaxDynamicSharedMemorySize,
                         SK_DYNSMEM);
    k_init<<<1, SK_NTHR>>>();
    k_main<<<SK_NBLK, SK_NTHR, SK_DYNSMEM>>>(C, out);
}

// round 17
// speedup vs baseline: 2.1683x; 1.3022x over previous
#include <cuda_runtime.h>
#include <cuda_bf16.h>

// Sinkhorn via linear-domain scaling, single persistent kernel:
//   prep:  each CTA computes bf16 E rows (bid*16..+15) AND bf16 E^T rows
//          (= C columns bid*16..+15) DIRECTLY from C into its 128 KB smem
//          cache -- no E gmem arrays, no read-back, no pre-iteration barrier.
//   iter:  a = p ./ (E b + P*b_pad);  b = p ./ (E^T a + P*a_pad)
//          128 persistent CTAs, counter grid barrier (tid0 release-add +
//          4 staggered acquire pollers), E rows register-prefetched from smem,
//          bf16 smem staging of the exchanged vector.
//   out:   out[i][j] = 4096 * min(1, a_i * b_j * exp(-C_ij/eps)), fp32 path.
//
// R17: SK_STEPS 13 -> 10 (iteration error at 13 measured ~0.14e-5 above the
// bf16 bias; x11 at 10 steps -> total ~5e-5) and direct-from-C smem prep
// (removes 32 MB of E gmem traffic + one grid barrier from the fixed cost).

#define SK_N     2048
#define SK_NT    4096
#define SK_STEPS 10
#define SK_NBLK  128
#define SK_NTHR  512
#define SK_DYNSMEM (128 * 1024)

__device__ float g_a[SK_N];
__device__ float g_b[SK_N];
__device__ unsigned g_count;                    // barrier arrival counter

// ---------------------------------------------------------------------------
__global__ void k_init() {
    int t = threadIdx.x;
    ((float4*)g_b)[t] = make_float4(1.0f, 1.0f, 1.0f, 1.0f);  // v0=0 -> b=1
    if (t == 0) g_count = 0u;
}

// ---------------------------------------------------------------------------
__device__ __forceinline__ float wred(float x) {
#pragma unroll
    for (int o = 16; o > 0; o >>= 1) x += __shfl_xor_sync(0xffffffffu, x, o);
    return x;
}

// Grid barrier: syncthreads (HB: all STGs before release) -> tid0
// release-arrive -> 4 staggered pollers with acquire loads; first detector
// stamps smem flag with this generation -> syncthreads.
__device__ __forceinline__ void grid_barrier(unsigned gen, unsigned target,
                                             volatile unsigned* sdone) {
    __syncthreads();
    if (threadIdx.x == 0) {
        asm volatile("red.release.gpu.global.add.u32 [%0], 1;"
                     :: "l"(&g_count) : "memory");
    }
    if ((threadIdx.x & 31) == 0 && threadIdx.x < 128) {   // warps 0..3, lane 0
        while (*sdone != gen) {
            unsigned c;
            asm volatile("ld.acquire.gpu.global.u32 %0, [%1];"
                         : "=r"(c) : "l"(&g_count) : "memory");
            if (c >= target) { *sdone = gen; break; }
        }
    }
    __syncthreads();
}

__device__ __forceinline__ float2 bf2f(unsigned u) {
    return __bfloat1622float2(*reinterpret_cast<__nv_bfloat162*>(&u));
}

// dot of 8 bf16 E values against 8 bf16 vec values (both uint4-packed)
__device__ __forceinline__ float dot8b(uint4 e, uint4 b, float acc) {
    float2 fe, fb;
    fe = bf2f(e.x); fb = bf2f(b.x);
    acc = fmaf(fe.x, fb.x, acc); acc = fmaf(fe.y, fb.y, acc);
    fe = bf2f(e.y); fb = bf2f(b.y);
    acc = fmaf(fe.x, fb.x, acc); acc = fmaf(fe.y, fb.y, acc);
    fe = bf2f(e.z); fb = bf2f(b.z);
    acc = fmaf(fe.x, fb.x, acc); acc = fmaf(fe.y, fb.y, acc);
    fe = bf2f(e.w); fb = bf2f(b.w);
    acc = fmaf(fe.x, fb.x, acc); acc = fmaf(fe.y, fb.y, acc);
    return acc;
}

// ---------------------------------------------------------------------------
__global__ void __launch_bounds__(SK_NTHR, 1) k_main(const float* __restrict__ C,
                                                     float* __restrict__ out) {
    extern __shared__ uint4 dynsmem[];   // [0..4096): E rows, [4096..8192): ET
    __shared__ uint4  svb[256];      // bf16 vec: uint4 m covers values m*8..+7
    __shared__ float  wsum[16];
    __shared__ unsigned sdone;       // barrier generation flag

    const int tid  = threadIdx.x;
    const int bid  = blockIdx.x;
    const int wid  = tid >> 5;
    const int lane = tid & 31;
    const float inv_eps = 20.0f;                // 1/0.05
    const float P     = 2048.0f;
    const float PMARG = 1.0f / 4096.0f;

    if (tid == 0) sdone = 0u;

    // ========= phase 0: E + E^T rows directly from C into smem =============
    // E rows: warp w computes row bid*16 + w (coalesced row-major C reads).
    // Packing: uint2 q covers bf16 cols 4q..4q+3 (low half = first col),
    // byte-identical to the proven row-major bf16 layout dot8b consumes.
    {
        const float4* Crow4 = (const float4*)(C + (size_t)(bid * 16 + wid) * SK_N);
        uint2* dstE = (uint2*)(dynsmem + wid * 256);
#pragma unroll
        for (int t = 0; t < 16; t++) {
            float4 v = Crow4[lane + 32 * t];
            __nv_bfloat162 lo = __floats2bfloat162_rn(__expf(-v.x * inv_eps),
                                                      __expf(-v.y * inv_eps));
            __nv_bfloat162 hi = __floats2bfloat162_rn(__expf(-v.z * inv_eps),
                                                      __expf(-v.w * inv_eps));
            uint2 st;
            st.x = *reinterpret_cast<unsigned*>(&lo);
            st.y = *reinterpret_cast<unsigned*>(&hi);
            dstE[lane + 32 * t] = st;
        }
    }
    // ET rows: ET[j][k] = exp(-C[k][bid*16+j]/eps). Thread (j = tid&15,
    // kq = tid>>4) covers k = kq + 32*t. Warp loads = 2 x 64B coalesced
    // segments; smem stores are 2-byte (conflicted but one-time).
    {
        const int j  = tid & 15;
        const int kq = tid >> 4;                 // 0..31
        __nv_bfloat16* dstT = (__nv_bfloat16*)(dynsmem + 4096) + j * SK_N;
        const float* Ccol = C + bid * 16 + j;
#pragma unroll 8
        for (int t = 0; t < 64; t++) {
            int k = kq + 32 * t;
            dstT[k] = __float2bfloat16(__expf(-Ccol[(size_t)k * SK_N] * inv_eps));
        }
    }
    __syncthreads();

    // ===================== phase 1: Sinkhorn iterations ======================
    const int row = bid * 16 + wid;              // one matrix row per warp
    const uint4* Erow  = dynsmem + wid * 256;          // 16 rows x 256 uint4
    const uint4* ETrow = dynsmem + 4096 + wid * 256;
    uint2* sv2 = (uint2*)svb;                    // uint2 t covers values t*4..+3

    uint4 eb[8];
#pragma unroll
    for (int k = 0; k < 8; k++) eb[k] = Erow[lane + 32 * k];

    float b_pad = 1.0f;
    float a_pad = 0.0f;
    unsigned gen = 0;

    for (int it = 0; it < SK_STEPS; ++it) {
        // ------------- row pass: a = p / (E b + P b_pad) -------------
        float4 v4 = __ldcg(((const float4*)g_b) + tid);
        {
            __nv_bfloat162 lo = __floats2bfloat162_rn(v4.x, v4.y);
            __nv_bfloat162 hi = __floats2bfloat162_rn(v4.z, v4.w);
            uint2 st;
            st.x = *reinterpret_cast<unsigned*>(&lo);
            st.y = *reinterpret_cast<unsigned*>(&hi);
            sv2[tid] = st;
        }
        float ps = wred(v4.x + v4.y + v4.z + v4.w);
        if (lane == 0) wsum[wid] = ps;
        __syncthreads();

        {
            float acc0 = 0.0f, acc1 = 0.0f, acc2 = 0.0f, acc3 = 0.0f;
#pragma unroll
            for (int k = 0; k < 8; k += 4) {
                acc0 = dot8b(eb[k+0], svb[lane + 32*(k+0)], acc0);
                acc1 = dot8b(eb[k+1], svb[lane + 32*(k+1)], acc1);
                acc2 = dot8b(eb[k+2], svb[lane + 32*(k+2)], acc2);
                acc3 = dot8b(eb[k+3], svb[lane + 32*(k+3)], acc3);
            }
            float acc = wred((acc0 + acc1) + (acc2 + acc3));
            if (lane == 0) g_a[row] = PMARG / (acc + P * b_pad);
        }

        // Prefetch ET row (from smem) for the col pass.
#pragma unroll
        for (int k = 0; k < 8; k++) eb[k] = ETrow[lane + 32 * k];

        // Scalar chain off the critical path.
        {
            float sum_b = 0.0f;
#pragma unroll
            for (int k = 0; k < 16; k++) sum_b += wsum[k];
            a_pad = PMARG / (sum_b + P * b_pad);
        }

        ++gen; grid_barrier(gen, gen * SK_NBLK, &sdone);

        // ------------- col pass: b = p / (E^T a + P a_pad) -------------
        float4 a4 = __ldcg(((const float4*)g_a) + tid);
        {
            __nv_bfloat162 lo = __floats2bfloat162_rn(a4.x, a4.y);
            __nv_bfloat162 hi = __floats2bfloat162_rn(a4.z, a4.w);
            uint2 st;
            st.x = *reinterpret_cast<unsigned*>(&lo);
            st.y = *reinterpret_cast<unsigned*>(&hi);
            sv2[tid] = st;
        }
        float pa = wred(a4.x + a4.y + a4.z + a4.w);
        if (lane == 0) wsum[wid] = pa;
        __syncthreads();

        {
            float acc0 = 0.0f, acc1 = 0.0f, acc2 = 0.0f, acc3 = 0.0f;
#pragma unroll
            for (int k = 0; k < 8; k += 4) {
                acc0 = dot8b(eb[k+0], svb[lane + 32*(k+0)], acc0);
                acc1 = dot8b(eb[k+1], svb[lane + 32*(k+1)], acc1);
                acc2 = dot8b(eb[k+2], svb[lane + 32*(k+2)], acc2);
                acc3 = dot8b(eb[k+3], svb[lane + 32*(k+3)], acc3);
            }
            float acc = wred((acc0 + acc1) + (acc2 + acc3));
            if (lane == 0) g_b[row] = PMARG / (acc + P * a_pad);
        }

        // Prefetch E row (from smem) for the next row pass.
#pragma unroll
        for (int k = 0; k < 8; k++) eb[k] = Erow[lane + 32 * k];

        {
            float sum_a = 0.0f;
#pragma unroll
            for (int k = 0; k < 16; k++) sum_a += wsum[k];
            b_pad = PMARG / (sum_a + P * a_pad);
        }

        ++gen; grid_barrier(gen, gen * SK_NBLK, &sdone);   // g_a, g_b complete
    }

    // ===================== phase 2: output ==================================
    // out[i][j] = 4096 * min(1, a_i * b_j * exp(-C_ij/eps)); pad blocks use
    // a_pad / b_pad (held in registers, identical in every CTA).
    {
        const float S = 4096.0f;
        const float4* B4 = (const float4*)g_b;
        for (int k = 0; k < 32; k++) {
            int i = bid + SK_NBLK * k;           // interleaved rows 0..4095
            float4* orow = (float4*)(out + (size_t)i * SK_NT);
            if (i < SK_N) {
                float ai = g_a[i];
                const float4* Cr = (const float4*)(C + (size_t)i * SK_N);
                float4 c = Cr[tid], b = B4[tid], r;
                r.x = S * fminf(1.0f, ai * b.x * __expf(-c.x * inv_eps));
                r.y = S * fminf(1.0f, ai * b.y * __expf(-c.y * inv_eps));
                r.z = S * fminf(1.0f, ai * b.z * __expf(-c.z * inv_eps));
                r.w = S * fminf(1.0f, ai * b.w * __expf(-c.w * inv_eps));
                orow[tid] = r;
                float cpad = S * fminf(1.0f, ai * b_pad);
                orow[512 + tid] = make_float4(cpad, cpad, cpad, cpad);
            } else {
                float4 b = B4[tid], r;
                r.x = S * fminf(1.0f, a_pad * b.x);
                r.y = S * fminf(1.0f, a_pad * b.y);
                r.z = S * fminf(1.0f, a_pad * b.z);
                r.w = S * fminf(1.0f, a_pad * b.w);
                orow[tid] = r;
                float cpad = S * fminf(1.0f, a_pad * b_pad);
                orow[512 + tid] = make_float4(cpad, cpad, cpad, cpad);
            }
        }
    }
}

// ---------------------------------------------------------------------------
extern "C" void kernel_launch(void* const* d_in, const int* in_sizes, int n_in,
                              void* d_out, int out_size) {
    const float* C = (const float*)d_in[0];
    float* out = (float*)d_out;

    cudaFuncSetAttribute(k_main, cudaFuncAttributeMaxDynamicSharedMemorySize,
                         SK_DYNSMEM);
    k_init<<<1, SK_NTHR>>>();
    k_main<<<SK_NBLK, SK_NTHR, SK_DYNSMEM>>>(C, out);
}